// round 4
// baseline (speedup 1.0000x reference)
#include <cuda_runtime.h>
#include <cuda_bf16.h>
#include <math.h>

#define T_  128
#define B_  32
#define D_  512
#define H_  512
#define N_  64
#define A_  32
#define G3_ 1536
#define NB_ 128

// ---------------- device scratch ----------------
__device__ float g_xT  [(size_t)T_*D_*B_];    // [t][k][b]
__device__ float g_wiT [(size_t)T_*G3_*B_];   // x@W_ih + bias_ih, [t][j][b]
__device__ float g_xmT [(size_t)T_*H_*B_];    // x@W_im, [t][m][b]
__device__ float g_hsT [(size_t)T_*H_*B_];    // hs outputs [t][m][b]
__device__ float g_hT     [H_*B_];
__device__ float g_pre    [H_*B_];
__device__ float g_accbot [H_*B_];
__device__ float g_entryT [H_*B_];
__device__ float g_hnewT  [H_*B_];
__device__ float g_mem [(size_t)B_*N_*H_];
__device__ float g_usage[B_*N_];
__device__ float g_lu   [N_*B_];              // sigmoid(usage), [n][b]
__device__ int   g_hard [B_];
__device__ unsigned g_cnt;
__device__ unsigned g_gen;

// ---------------- grid-wide barrier (generation counter) ----------------
__device__ __forceinline__ void grid_sync_dev(unsigned nb) {
    __syncthreads();
    if (threadIdx.x == 0) {
        __threadfence();
        unsigned g = *((volatile unsigned*)&g_gen);
        unsigned arrived = atomicAdd(&g_cnt, 1u);
        if (arrived == nb - 1u) {
            g_cnt = 0u;
            __threadfence();
            *((volatile unsigned*)&g_gen) = g + 1u;
        } else {
            while (*((volatile unsigned*)&g_gen) == g) { __nanosleep(64); }
            __threadfence();
        }
    }
    __syncthreads();
}

// ---------------- init ----------------
__global__ void k_init() {
    size_t i = (size_t)blockIdx.x * blockDim.x + threadIdx.x;
    size_t stride = (size_t)gridDim.x * blockDim.x;
    for (size_t j = i; j < (size_t)B_*N_*H_; j += stride) g_mem[j] = 0.f;
    if (i < (size_t)H_*B_) g_hT[i] = 0.f;
    if (i < (size_t)B_*N_) { g_usage[i] = -99999.f; }
    if (i < (size_t)N_*B_) { g_lu[i] = 0.f; }
    if (i < B_) g_hard[i] = 0;
}

// ---------------- transpose x[t][b][k] -> g_xT[t][k][b], smem-tiled ----------------
__global__ void k_transpose(const float* __restrict__ x) {
    __shared__ float tile[32][33];
    int t = blockIdx.x;
    int w = threadIdx.x >> 5, lane = threadIdx.x & 31;   // 16 warps
    for (int k0 = 0; k0 < D_; k0 += 32) {
#pragma unroll
        for (int bb = 0; bb < 32; bb += 16) {
            int b = w + bb;
            tile[b][lane] = x[((size_t)(t*B_ + b))*D_ + k0 + lane];
        }
        __syncthreads();
#pragma unroll
        for (int kk = 0; kk < 32; kk += 16) {
            int k = k0 + w + kk;
            g_xT[((size_t)t*D_ + k)*B_ + lane] = tile[lane][w + kk];
        }
        __syncthreads();
    }
}

// ---------------- precompute x@W_ih (+bias_ih) and x@W_im ----------------
__global__ void k_pregemm(const float* __restrict__ W_ih,
                          const float* __restrict__ W_im,
                          const float* __restrict__ bias) {
    int warp = threadIdx.x >> 5, lane = threadIdx.x & 31;
    int t = blockIdx.x >> 5;
    int r = ((blockIdx.x & 31) << 3) + warp;   // 0..255
    const float* X = g_xT + (size_t)t * D_ * B_;
    float acc[8];
#pragma unroll
    for (int i = 0; i < 8; i++) acc[i] = 0.f;

    if (r < 192) {
        int j0 = r << 3;
        const float* W = W_ih + j0;
#pragma unroll 4
        for (int k = 0; k < D_; k++) {
            float xv = X[k*B_ + lane];
            float4 w0 = *(const float4*)(W + (size_t)k*G3_);
            float4 w1 = *(const float4*)(W + (size_t)k*G3_ + 4);
            acc[0] += xv*w0.x; acc[1] += xv*w0.y; acc[2] += xv*w0.z; acc[3] += xv*w0.w;
            acc[4] += xv*w1.x; acc[5] += xv*w1.y; acc[6] += xv*w1.z; acc[7] += xv*w1.w;
        }
        float* o = g_wiT + ((size_t)t*G3_ + j0)*B_ + lane;
#pragma unroll
        for (int i = 0; i < 8; i++) o[(size_t)i*B_] = acc[i] + bias[j0 + i];
    } else {
        int m0 = (r - 192) << 3;
        const float* W = W_im + m0;
#pragma unroll 4
        for (int k = 0; k < D_; k++) {
            float xv = X[k*B_ + lane];
            float4 w0 = *(const float4*)(W + (size_t)k*H_);
            float4 w1 = *(const float4*)(W + (size_t)k*H_ + 4);
            acc[0] += xv*w0.x; acc[1] += xv*w0.y; acc[2] += xv*w0.z; acc[3] += xv*w0.w;
            acc[4] += xv*w1.x; acc[5] += xv*w1.y; acc[6] += xv*w1.z; acc[7] += xv*w1.w;
        }
        float* o = g_xmT + ((size_t)t*H_ + m0)*B_ + lane;
#pragma unroll
        for (int i = 0; i < 8; i++) o[(size_t)i*B_] = acc[i];
    }
}

// ---------------- persistent recurrence kernel ----------------
__global__ void __launch_bounds__(512, 1) k_step(
    const float* __restrict__ W_hm, const float* __restrict__ W_um,
    const float* __restrict__ fc1_w, const float* __restrict__ fc1_b,
    const float* __restrict__ fc2_w, const float* __restrict__ fc2_b,
    const float* __restrict__ W_hh, const float* __restrict__ bias,
    const float* __restrict__ u_noise, const int* __restrict__ length)
{
    __shared__ float sm[16*384];
    __shared__ int sIdx;
    const int warp = threadIdx.x >> 5, lane = threadIdx.x & 31;
    const unsigned nb = gridDim.x;

    for (int t = 0; t < T_; t++) {
        // ===== Phase A: pre = tanh(xm + h@W_hm + lu@W_um); accbot = h@fc2_w[H:]; mem write =====
        for (int p = blockIdx.x; p < 288; p += nb) {
            if (p < 256) {
                const bool isPre = (p < 128);
                const int m0 = (isPre ? p : (p - 128)) << 2;
                const float* W = isPre ? (W_hm + m0) : (fc2_w + (size_t)H_*H_ + m0);
                float a0=0.f, a1=0.f, a2=0.f, a3=0.f;
                const int k0 = warp << 5;
                const float* Xp = g_hT + k0*B_ + lane;
                const float* Wp = W + (size_t)k0*H_;
#pragma unroll 8
                for (int k = 0; k < 32; k++) {
                    float xv = Xp[k*B_];
                    float4 wv = *(const float4*)(Wp + (size_t)k*H_);
                    a0 += xv*wv.x; a1 += xv*wv.y; a2 += xv*wv.z; a3 += xv*wv.w;
                }
                if (isPre && warp < 2) {
                    const int n0 = warp << 5;
#pragma unroll 8
                    for (int n = 0; n < 32; n++) {
                        float xv = g_lu[(n0 + n)*B_ + lane];
                        float4 wv = *(const float4*)(W_um + (size_t)(n0 + n)*H_ + m0);
                        a0 += xv*wv.x; a1 += xv*wv.y; a2 += xv*wv.z; a3 += xv*wv.w;
                    }
                }
                float* s = sm + warp*128;
                s[0*32+lane]=a0; s[1*32+lane]=a1; s[2*32+lane]=a2; s[3*32+lane]=a3;
                __syncthreads();
                if (threadIdx.x < 128) {
                    int c = threadIdx.x >> 5, b = threadIdx.x & 31;
                    float v = 0.f;
#pragma unroll
                    for (int w = 0; w < 16; w++) v += sm[w*128 + c*32 + b];
                    int m = m0 + c;
                    if (isPre) {
                        v += g_xmT[((size_t)t*H_ + m)*B_ + b];
                        g_pre[m*B_ + b] = tanhf(v);
                    } else {
                        g_accbot[m*B_ + b] = v;
                    }
                }
                __syncthreads();
            } else {
                int b = p - 256;
                int s = (t < N_) ? t : g_hard[b];
                float* mp = g_mem + ((size_t)b*N_ + s)*H_;
                for (int k = threadIdx.x; k < H_; k += 512)
                    mp[k] = g_hT[k*B_ + b];
            }
        }
        grid_sync_dev(nb);

        // ===== Phase B: read_head=pre@fc1_w+fc1_b+gumbel; argmax; usage/lu; entry gather =====
        for (int p = blockIdx.x; p < B_; p += nb) {
            const int b = p;
            {
                int half = warp & 1, seg = warp >> 1;
                int n = (half << 5) + lane;
                float acc = 0.f;
                int mbase = seg << 6;
                const float* Pp = g_pre + mbase*B_ + b;
                const float* Fp = fc1_w + (size_t)mbase*N_ + n;
#pragma unroll 8
                for (int m = 0; m < 64; m++) acc += Pp[m*B_] * Fp[(size_t)m*N_];
                sm[seg*64 + n] = acc;
            }
            __syncthreads();
            if (warp == 0) {
                float bv = -1e30f; int bi = 0;
#pragma unroll
                for (int j = 0; j < 2; j++) {
                    int n = lane + (j << 5);
                    float s = fc1_b[n];
#pragma unroll
                    for (int sg = 0; sg < 8; sg++) s += sm[sg*64 + n];
                    double u = (double)u_noise[((size_t)t*B_ + b)*N_ + n];
                    double gg = -log(1e-20 - log(1e-20 + u));
                    float v = s + (float)gg;
                    if (v > bv) { bv = v; bi = n; }
                }
#pragma unroll
                for (int off = 16; off; off >>= 1) {
                    float ov = __shfl_down_sync(0xffffffffu, bv, off);
                    int   oi = __shfl_down_sync(0xffffffffu, bi, off);
                    if (ov > bv || (ov == bv && oi < bi)) { bv = ov; bi = oi; }
                }
                if (lane == 0) { sIdx = bi; g_hard[b] = bi; }
            }
            __syncthreads();
            const int idx = sIdx;
            if (threadIdx.x < N_) {
                int n = threadIdx.x;
                float u = g_usage[b*N_ + n];
                float un = (n == idx) ? 0.f : (u - 1.f);
                g_usage[b*N_ + n] = un;
                g_lu[n*B_ + b] = 1.f / (1.f + expf(-un));
            }
            const float* mp = g_mem + ((size_t)b*N_ + idx)*H_;
            for (int k = threadIdx.x; k < H_; k += 512)
                g_entryT[k*B_ + b] = mp[k];
            __syncthreads();
        }
        grid_sync_dev(nb);

        // ===== Phase D: h_new = entry@fc2_w[:H] + accbot + fc2_b =====
        for (int p = blockIdx.x; p < 128; p += nb) {
            const int m0 = p << 2;
            float a0=0.f, a1=0.f, a2=0.f, a3=0.f;
            const int k0 = warp << 5;
            const float* Xp = g_entryT + k0*B_ + lane;
            const float* Wp = fc2_w + (size_t)k0*H_ + m0;
#pragma unroll 8
            for (int k = 0; k < 32; k++) {
                float xv = Xp[k*B_];
                float4 wv = *(const float4*)(Wp + (size_t)k*H_);
                a0 += xv*wv.x; a1 += xv*wv.y; a2 += xv*wv.z; a3 += xv*wv.w;
            }
            float* s = sm + warp*128;
            s[0*32+lane]=a0; s[1*32+lane]=a1; s[2*32+lane]=a2; s[3*32+lane]=a3;
            __syncthreads();
            if (threadIdx.x < 128) {
                int c = threadIdx.x >> 5, b = threadIdx.x & 31;
                float v = 0.f;
#pragma unroll
                for (int w = 0; w < 16; w++) v += sm[w*128 + c*32 + b];
                int m = m0 + c;
                g_hnewT[m*B_ + b] = v + g_accbot[m*B_ + b] + fc2_b[m];
            }
            __syncthreads();
        }
        grid_sync_dev(nb);

        // ===== Phase E: wh = h_new@W_hh + bias_hh (r,z,n fused); gates; mask; store =====
        for (int p = blockIdx.x; p < 128; p += nb) {
            const int m0 = p << 2;
            float a[12];
#pragma unroll
            for (int i = 0; i < 12; i++) a[i] = 0.f;
            const int k0 = warp << 5;
            const float* Xp = g_hnewT + k0*B_ + lane;
            const float* Wp = W_hh + (size_t)k0*G3_;
#pragma unroll 4
            for (int k = 0; k < 32; k++) {
                float xv = Xp[k*B_];
                float4 wr = *(const float4*)(Wp + (size_t)k*G3_ + m0);
                float4 wz = *(const float4*)(Wp + (size_t)k*G3_ + 512 + m0);
                float4 wn = *(const float4*)(Wp + (size_t)k*G3_ + 1024 + m0);
                a[0]+=xv*wr.x; a[1]+=xv*wr.y; a[2]+=xv*wr.z; a[3]+=xv*wr.w;
                a[4]+=xv*wz.x; a[5]+=xv*wz.y; a[6]+=xv*wz.z; a[7]+=xv*wz.w;
                a[8]+=xv*wn.x; a[9]+=xv*wn.y; a[10]+=xv*wn.z; a[11]+=xv*wn.w;
            }
            float* s = sm + warp*384;
#pragma unroll
            for (int c = 0; c < 12; c++) s[c*32+lane] = a[c];
            __syncthreads();
            if (threadIdx.x < 128) {
                int c = threadIdx.x >> 5, b = threadIdx.x & 31;
                float rv=0.f, zv=0.f, nv=0.f;
#pragma unroll
                for (int w = 0; w < 16; w++) {
                    rv += sm[w*384 +       c*32 + b];
                    zv += sm[w*384 + 128 + c*32 + b];
                    nv += sm[w*384 + 256 + c*32 + b];
                }
                int m = m0 + c;
                const float* wi = g_wiT + (size_t)t*G3_*B_;
                float ri = wi[(size_t)m*B_ + b];
                float zi = wi[(size_t)(512+m)*B_ + b];
                float ni = wi[(size_t)(1024+m)*B_ + b];
                float hn = g_hnewT[m*B_ + b];
                float rh = rv + bias[3*H_ + m];
                float zh = zv + bias[3*H_ + 512 + m];
                float nh = nv + bias[3*H_ + 1024 + m];
                float r = 1.f/(1.f+expf(-(ri+rh)));
                float z = 1.f/(1.f+expf(-(zi+zh)));
                float nn = tanhf(ni + r*nh);
                float h1 = (1.f - z)*nn + z*hn;
                float hprev = g_hT[m*B_ + b];
                float h2 = (t < length[b]) ? h1 : hprev;
                g_hT[m*B_ + b] = h2;
                g_hsT[((size_t)t*H_ + m)*B_ + b] = h2;
            }
            __syncthreads();
        }
        grid_sync_dev(nb);
    }
}

// ---------------- final: out[t][b][a] = hs[t][b]@fc_w + fc_b ----------------
__global__ void k_out(const float* __restrict__ fc_w,
                      const float* __restrict__ fc_b,
                      float* __restrict__ out) {
    int t = blockIdx.x;
    int warp = threadIdx.x >> 5, lane = threadIdx.x & 31;
    int a0 = warp * 2;
    float acc0 = 0.f, acc1 = 0.f;
    const float* Xp = g_hsT + (size_t)t*H_*B_ + lane;
#pragma unroll 4
    for (int k = 0; k < H_; k++) {
        float xv = Xp[k*B_];
        float2 w = *(const float2*)(fc_w + (size_t)k*A_ + a0);
        acc0 += xv*w.x; acc1 += xv*w.y;
    }
    float* o = out + ((size_t)t*B_ + lane)*A_;
    o[a0]     = acc0 + fc_b[a0];
    o[a0 + 1] = acc1 + fc_b[a0 + 1];
}

extern "C" void kernel_launch(void* const* d_in, const int* in_sizes, int n_in,
                              void* d_out, int out_size) {
    (void)in_sizes; (void)n_in; (void)out_size;
    const float* x       = (const float*)d_in[0];
    const int*   length  = (const int*)  d_in[1];
    const float* u_noise = (const float*)d_in[2];
    const float* W_ih    = (const float*)d_in[3];
    const float* W_hh    = (const float*)d_in[4];
    const float* bias    = (const float*)d_in[5];
    const float* W_im    = (const float*)d_in[6];
    const float* W_hm    = (const float*)d_in[7];
    const float* W_um    = (const float*)d_in[8];
    const float* fc1_w   = (const float*)d_in[9];
    const float* fc1_b   = (const float*)d_in[10];
    const float* fc2_w   = (const float*)d_in[11];
    const float* fc2_b   = (const float*)d_in[12];
    const float* fc_w    = (const float*)d_in[13];
    const float* fc_b    = (const float*)d_in[14];
    float* out = (float*)d_out;

    k_init<<<256, 256>>>();
    k_transpose<<<T_, 512>>>(x);
    k_pregemm<<<T_*32, 256>>>(W_ih, W_im, bias);
    k_step<<<NB_, 512>>>(W_hm, W_um, fc1_w, fc1_b, fc2_w, fc2_b,
                         W_hh, bias, u_noise, length);
    k_out<<<T_, 512>>>(fc_w, fc_b, out);
}